// round 5
// baseline (speedup 1.0000x reference)
#include <cuda_runtime.h>
#include <cuda_fp16.h>
#include <mma.h>
#include <cstdint>

using namespace nvcuda;

#define N_NODES 50000
#define PAD_NODES 50048      // 391 * 128 — GEMM epilogues store unguarded
#define N_EDGES 800000
#define F_IN    512
#define F_HID   128
#define F_OUT   64
#define NBLK    196          // ceil(50000/256)

// ---------------- device scratch (static; no allocation allowed) -------------
__device__ int    g_indeg[N_NODES];
__device__ int    g_outdeg[N_NODES];
__device__ float  g_outnorm[N_NODES];
__device__ float  g_innorm[N_NODES];
__device__ int    g_blk_agg[NBLK];
__device__ int    g_blk_flag[NBLK];
__device__ int    g_off[N_NODES + 1];
__device__ int    g_cursor[N_NODES];
__device__ int    g_csr[N_EDGES];
__device__ __half g_y1h[(size_t)PAD_NODES * F_HID];
__device__ __half g_hh [(size_t)N_NODES  * F_HID];
__device__ __half g_y2h[(size_t)PAD_NODES * F_OUT];

__device__ __forceinline__ float tf32_rna_f(float f) {
    uint32_t r; asm("cvt.rna.tf32.f32 %0, %1;" : "=r"(r) : "f"(f));
    return __uint_as_float(r);
}

// ---------------- degree init ------------------------------------------------
__global__ void k_zero_deg() {
    int i = blockIdx.x * blockDim.x + threadIdx.x;
    if (i < N_NODES) { g_indeg[i] = 0; g_outdeg[i] = 0; }
    if (i < NBLK)    { g_blk_flag[i] = 0; }
}

__global__ void k_degrees(const int* __restrict__ esrc, const int* __restrict__ edst) {
    int e = blockIdx.x * blockDim.x + threadIdx.x;
    if (e < N_EDGES) {
        atomicAdd(&g_outdeg[esrc[e]], 1);
        atomicAdd(&g_indeg [edst[e]], 1);
    }
}

// ---------------- fused scan: offsets + cursor + norms in ONE kernel ---------
// Per-block scan, publish aggregate, warp-window lookback over predecessors
// (aggregates publish independently -> no serial chain, no deadlock: blocks
// only wait on lower block ids).
__global__ void k_scan_fused() {
    __shared__ int sh[256];
    __shared__ int s_prefix;
    const int t = threadIdx.x;
    const int b = blockIdx.x;
    const int i = b * 256 + t;

    int v = (i < N_NODES) ? g_indeg[i] : 0;
    sh[t] = v;
    __syncthreads();
    #pragma unroll
    for (int o = 1; o < 256; o <<= 1) {
        int x = (t >= o) ? sh[t - o] : 0;
        __syncthreads();
        sh[t] += x;
        __syncthreads();
    }
    // publish this block's aggregate ASAP
    if (t == 255) {
        *(volatile int*)&g_blk_agg[b] = sh[255];
        __threadfence();
        *(volatile int*)&g_blk_flag[b] = 1;
    }
    // warp 0: sum all predecessor aggregates (windows of 32, parallel publish)
    if (t < 32) {
        int sum = 0;
        for (int w0 = 0; w0 < b; w0 += 32) {
            int idx = w0 + t;
            int val = 0;
            if (idx < b) {
                while (*(volatile int*)&g_blk_flag[idx] == 0) { }
                val = *(volatile int*)&g_blk_agg[idx];
            }
            #pragma unroll
            for (int o = 16; o > 0; o >>= 1)
                val += __shfl_xor_sync(0xFFFFFFFFu, val, o);
            sum += val;
        }
        if (t == 0) s_prefix = sum;
    }
    __syncthreads();
    if (i < N_NODES) {
        int incl = sh[t] + s_prefix;
        int deg  = v;
        g_off[i + 1]  = incl;
        g_cursor[i]   = incl - deg;
        if (i == 0) g_off[0] = 0;
        g_outnorm[i] = rsqrtf(fmaxf((float)g_outdeg[i], 1.0f));
        g_innorm [i] = rsqrtf(fmaxf((float)deg, 1.0f));
    }
}

__global__ void k_scatter(const int* __restrict__ esrc, const int* __restrict__ edst) {
    int e = blockIdx.x * blockDim.x + threadIdx.x;
    if (e < N_EDGES) {
        int d = edst[e];
        int p = atomicAdd(&g_cursor[d], 1);
        g_csr[p] = esrc[e];
    }
}

// ---------------- WMMA tf32 GEMM, double-buffered, fp16 output ---------------
// Y_half[M,BN] = ((A * outnorm[:,None]) @ W)  ; A fp32 (L1) or fp16 g_hh (L2)
// BM=128, BK=32, 256 thr / 8 warps (4M x 2N), warp tile 32 x BN/2.
template <int BN, int KT, int LAYER>
__global__ void __launch_bounds__(256) k_wmma_gemm(const float* __restrict__ Ain,
                                                   const float* __restrict__ W) {
    constexpr int BM  = 128;
    constexpr int BK  = 32;
    constexpr int NC  = KT / BK;
    constexpr int LDA = 40;
    constexpr int LDB = BN + 4;
    constexpr int WN  = BN / 2;
    constexpr int FN  = WN / 16;
    constexpr int NQB = (BK * BN / 4) / 256;   // float4 B loads per thread

    extern __shared__ float smem[];
    float* sA0 = smem;
    float* sA1 = sA0 + BM * LDA;
    float* sB0 = sA1 + BM * LDA;
    float* sB1 = sB0 + BK * LDB;
    float* sAbuf[2] = { sA0, sA1 };
    float* sBbuf[2] = { sB0, sB1 };
    float* stage = smem;                       // epilogue staging (aliases bufs)

    const int tid = threadIdx.x;
    const int wid = tid >> 5;
    const int lane = tid & 31;
    const int wm  = wid >> 1;
    const int wn  = wid & 1;
    const int m0  = blockIdx.x * BM;

    wmma::fragment<wmma::accumulator, 16, 16, 8, float> c[2][FN];
    #pragma unroll
    for (int i = 0; i < 2; i++)
        #pragma unroll
        for (int j = 0; j < FN; j++) wmma::fill_fragment(c[i][j], 0.0f);

    const int arow  = tid >> 1;
    const int acol0 = (tid & 1) * 16;
    const int growA = m0 + arow;
    const bool okA  = growA < N_NODES;
    const float sc  = okA ? g_outnorm[growA] : 0.0f;

    // staging registers
    float4 ra[4];          // 16 fp32 A elems (layer 1)
    uint4  rah[2];         // 16 fp16 A elems (layer 2)
    float4 rb[NQB];

    auto loadA = [&](int k0) {
        if constexpr (LAYER == 1) {
            const float* Arow = Ain + (size_t)growA * KT + k0 + acol0;
            #pragma unroll
            for (int q = 0; q < 4; q++)
                ra[q] = okA ? *(const float4*)(Arow + q * 4)
                            : make_float4(0.f, 0.f, 0.f, 0.f);
        } else {
            const __half* Arow = g_hh + (size_t)growA * KT + k0 + acol0;
            #pragma unroll
            for (int q = 0; q < 2; q++)
                rah[q] = okA ? *(const uint4*)(Arow + q * 8)
                             : make_uint4(0u, 0u, 0u, 0u);
        }
    };
    auto storeA = [&](float* buf) {
        if constexpr (LAYER == 1) {
            #pragma unroll
            for (int q = 0; q < 4; q++) {
                float4 t;
                t.x = tf32_rna_f(ra[q].x * sc);
                t.y = tf32_rna_f(ra[q].y * sc);
                t.z = tf32_rna_f(ra[q].z * sc);
                t.w = tf32_rna_f(ra[q].w * sc);
                *(float4*)&buf[arow * LDA + acol0 + q * 4] = t;
            }
        } else {
            #pragma unroll
            for (int q = 0; q < 2; q++) {
                const uint32_t u[4] = { rah[q].x, rah[q].y, rah[q].z, rah[q].w };
                #pragma unroll
                for (int p = 0; p < 4; p++) {
                    float2 f = __half22float2(*(const __half2*)&u[p]);
                    float2 t;
                    t.x = tf32_rna_f(f.x * sc);
                    t.y = tf32_rna_f(f.y * sc);
                    *(float2*)&buf[arow * LDA + acol0 + q * 8 + p * 2] = t;
                }
            }
        }
    };
    auto loadB = [&](int k0) {
        #pragma unroll
        for (int q = 0; q < NQB; q++) {
            int i = tid + q * 256;
            int r = i / (BN / 4);
            int cc = (i % (BN / 4)) * 4;
            rb[q] = *(const float4*)&W[(size_t)(k0 + r) * BN + cc];
        }
    };
    auto storeB = [&](float* buf) {
        #pragma unroll
        for (int q = 0; q < NQB; q++) {
            int i = tid + q * 256;
            int r = i / (BN / 4);
            int cc = (i % (BN / 4)) * 4;
            float4 t;
            t.x = tf32_rna_f(rb[q].x);
            t.y = tf32_rna_f(rb[q].y);
            t.z = tf32_rna_f(rb[q].z);
            t.w = tf32_rna_f(rb[q].w);
            *(float4*)&buf[r * LDB + cc] = t;
        }
    };

    // prologue
    loadA(0); loadB(0);
    storeA(sAbuf[0]); storeB(sBbuf[0]);
    __syncthreads();

    #pragma unroll 1
    for (int cidx = 0; cidx < NC; cidx++) {
        const int b = cidx & 1;
        if (cidx + 1 < NC) { loadA((cidx + 1) * BK); loadB((cidx + 1) * BK); }
        // compute current buffer
        #pragma unroll
        for (int kk = 0; kk < BK; kk += 8) {
            wmma::fragment<wmma::matrix_a, 16, 16, 8, wmma::precision::tf32, wmma::row_major> a[2];
            wmma::fragment<wmma::matrix_b, 16, 16, 8, wmma::precision::tf32, wmma::row_major> bf[FN];
            #pragma unroll
            for (int i = 0; i < 2; i++)
                wmma::load_matrix_sync(a[i], &sAbuf[b][(wm * 32 + i * 16) * LDA + kk], LDA);
            #pragma unroll
            for (int j = 0; j < FN; j++)
                wmma::load_matrix_sync(bf[j], &sBbuf[b][kk * LDB + wn * WN + j * 16], LDB);
            #pragma unroll
            for (int i = 0; i < 2; i++)
                #pragma unroll
                for (int j = 0; j < FN; j++)
                    wmma::mma_sync(c[i][j], a[i], bf[j], c[i][j]);
        }
        __syncthreads();
        if (cidx + 1 < NC) {
            storeA(sAbuf[1 - b]); storeB(sBbuf[1 - b]);
            __syncthreads();
        }
    }

    // epilogue: frags -> per-warp smem tile -> half2 global
    __half* Yh = (LAYER == 1) ? g_y1h : g_y2h;
    float* wtile = stage + wid * (32 * WN);
    #pragma unroll
    for (int i = 0; i < 2; i++)
        #pragma unroll
        for (int j = 0; j < FN; j++)
            wmma::store_matrix_sync(wtile + i * 16 * WN + j * 16, c[i][j], WN,
                                    wmma::mem_row_major);
    __syncwarp();
    {
        const float* srow = wtile + lane * WN;
        __half* drow = Yh + (size_t)(m0 + wm * 32 + lane) * BN + wn * WN;
        #pragma unroll
        for (int k2 = 0; k2 < WN / 2; k2++) {
            float2 f = *(const float2*)(srow + k2 * 2);
            *(__half2*)(drow + k2 * 2) = __float22half2_rn(f);
        }
    }
}

// ---------------- aggregation (CSR gather, fp16 payload) ---------------------
__global__ void __launch_bounds__(256) k_agg1(const float* __restrict__ b1) {
    int warp = (blockIdx.x * blockDim.x + threadIdx.x) >> 5;
    int lane = threadIdx.x & 31;
    if (warp >= N_NODES) return;
    int beg = g_off[warp], end = g_off[warp + 1];
    float4 acc = make_float4(0.f, 0.f, 0.f, 0.f);
    for (int j = beg; j < end; j++) {
        int s = g_csr[j];
        uint2 u = *(const uint2*)&g_y1h[(size_t)s * F_HID + lane * 4];
        float2 f0 = __half22float2(*(const __half2*)&u.x);
        float2 f1 = __half22float2(*(const __half2*)&u.y);
        acc.x += f0.x; acc.y += f0.y; acc.z += f1.x; acc.w += f1.y;
    }
    float inn = g_innorm[warp];
    float4 bb = *(const float4*)&b1[lane * 4];
    float2 o0, o1;
    o0.x = fmaxf(fmaf(acc.x, inn, bb.x), 0.f);
    o0.y = fmaxf(fmaf(acc.y, inn, bb.y), 0.f);
    o1.x = fmaxf(fmaf(acc.z, inn, bb.z), 0.f);
    o1.y = fmaxf(fmaf(acc.w, inn, bb.w), 0.f);
    uint2 u;
    *(__half2*)&u.x = __float22half2_rn(o0);
    *(__half2*)&u.y = __float22half2_rn(o1);
    *(uint2*)&g_hh[(size_t)warp * F_HID + lane * 4] = u;
}

__global__ void __launch_bounds__(256) k_agg2(const float* __restrict__ b2,
                                              float* __restrict__ out) {
    int warp = (blockIdx.x * blockDim.x + threadIdx.x) >> 5;
    int lane = threadIdx.x & 31;
    if (warp >= N_NODES) return;
    int beg = g_off[warp], end = g_off[warp + 1];
    float2 acc = make_float2(0.f, 0.f);
    for (int j = beg; j < end; j++) {
        int s = g_csr[j];
        __half2 h = *(const __half2*)&g_y2h[(size_t)s * F_OUT + lane * 2];
        float2 f = __half22float2(h);
        acc.x += f.x; acc.y += f.y;
    }
    float inn = g_innorm[warp];
    float2 bb = *(const float2*)&b2[lane * 2];
    float2 o;
    o.x = fmaf(acc.x, inn, bb.x);
    o.y = fmaf(acc.y, inn, bb.y);
    *(float2*)&out[(size_t)warp * F_OUT + lane * 2] = o;
}

// ---------------- launch -----------------------------------------------------
extern "C" void kernel_launch(void* const* d_in, const int* in_sizes, int n_in,
                              void* d_out, int out_size) {
    const float* features = (const float*)d_in[0];
    const int*   esrc     = (const int*)  d_in[1];
    const int*   edst     = (const int*)  d_in[2];
    const float* W1       = (const float*)d_in[3];
    const float* b1       = (const float*)d_in[4];
    const float* W2       = (const float*)d_in[5];
    const float* b2       = (const float*)d_in[6];
    float* out = (float*)d_out;

    const int EB = (N_EDGES + 255) / 256;     // 3125
    const int GB = (N_NODES + 127) / 128;     // 391

    // dynamic smem sizes (floats): 2*A + 2*B buffers; epilogue aliases.
    const int SM1 = (2 * 128 * 40 + 2 * 32 * (128 + 4)) * 4;  // 74752 B
    const int SM2 = (2 * 128 * 40 + 2 * 32 * (64 + 4))  * 4;  // 58368 B
    static bool attr_set = false;
    cudaFuncSetAttribute(k_wmma_gemm<128, 512, 1>,
                         cudaFuncAttributeMaxDynamicSharedMemorySize, SM1);
    cudaFuncSetAttribute(k_wmma_gemm<64, 128, 2>,
                         cudaFuncAttributeMaxDynamicSharedMemorySize, SM2);
    (void)attr_set;

    k_zero_deg  <<<NBLK, 256>>>();
    k_degrees   <<<EB, 256>>>(esrc, edst);
    k_scan_fused<<<NBLK, 256>>>();
    k_scatter   <<<EB, 256>>>(esrc, edst);

    k_wmma_gemm<128, 512, 1><<<GB, 256, SM1>>>(features, W1);
    k_agg1<<<(N_NODES * 32 + 255) / 256, 256>>>(b1);
    k_wmma_gemm<64, 128, 2><<<GB, 256, SM2>>>(nullptr, W2);
    k_agg2<<<(N_NODES * 32 + 255) / 256, 256>>>(b2, out);
}

// round 6
// speedup vs baseline: 1.0312x; 1.0312x over previous
#include <cuda_runtime.h>
#include <cuda_fp16.h>
#include <mma.h>
#include <cstdint>

using namespace nvcuda;

#define N_NODES 50000
#define PAD_NODES 50048      // 391 * 128 — GEMM epilogues store unguarded
#define N_EDGES 800000
#define F_IN    512
#define F_HID   128
#define F_OUT   64
#define NBLK    196          // ceil(50000/256)

// ---------------- device scratch (static; no allocation allowed) -------------
__device__ int    g_indeg[N_NODES];
__device__ int    g_outdeg[N_NODES];
__device__ float  g_outnorm[N_NODES];
__device__ float  g_innorm[N_NODES];
__device__ int    g_blk_agg[NBLK];
__device__ int    g_blk_flag[NBLK];
__device__ int    g_off[N_NODES + 1];
__device__ int    g_cursor[N_NODES];
__device__ int    g_csr[N_EDGES];
__device__ __half g_y1h[(size_t)PAD_NODES * F_HID];
__device__ __half g_hh [(size_t)N_NODES  * F_HID];
__device__ __half g_y2h[(size_t)PAD_NODES * F_OUT];

__device__ __forceinline__ float tf32_rna_f(float f) {
    uint32_t r; asm("cvt.rna.tf32.f32 %0, %1;" : "=r"(r) : "f"(f));
    return __uint_as_float(r);
}

// ---------------- degree init ------------------------------------------------
__global__ void k_zero_deg() {
    int i = blockIdx.x * blockDim.x + threadIdx.x;
    if (i < N_NODES) { g_indeg[i] = 0; g_outdeg[i] = 0; }
    if (i < NBLK)    { g_blk_flag[i] = 0; }
}

__global__ void k_degrees(const int* __restrict__ esrc, const int* __restrict__ edst) {
    int e = blockIdx.x * blockDim.x + threadIdx.x;
    if (e < N_EDGES) {
        atomicAdd(&g_outdeg[esrc[e]], 1);   // no return use -> REDG
        atomicAdd(&g_indeg [edst[e]], 1);
    }
}

// ---------------- fused scan: offsets + cursor + norms in ONE kernel ---------
__global__ void k_scan_fused() {
    __shared__ int sh[256];
    __shared__ int s_prefix;
    const int t = threadIdx.x;
    const int b = blockIdx.x;
    const int i = b * 256 + t;

    int v = (i < N_NODES) ? g_indeg[i] : 0;
    sh[t] = v;
    __syncthreads();
    #pragma unroll
    for (int o = 1; o < 256; o <<= 1) {
        int x = (t >= o) ? sh[t - o] : 0;
        __syncthreads();
        sh[t] += x;
        __syncthreads();
    }
    if (t == 255) {
        *(volatile int*)&g_blk_agg[b] = sh[255];
        __threadfence();
        *(volatile int*)&g_blk_flag[b] = 1;
    }
    if (t < 32) {
        int sum = 0;
        for (int w0 = 0; w0 < b; w0 += 32) {
            int idx = w0 + t;
            int val = 0;
            if (idx < b) {
                while (*(volatile int*)&g_blk_flag[idx] == 0) { }
                val = *(volatile int*)&g_blk_agg[idx];
            }
            #pragma unroll
            for (int o = 16; o > 0; o >>= 1)
                val += __shfl_xor_sync(0xFFFFFFFFu, val, o);
            sum += val;
        }
        if (t == 0) s_prefix = sum;
    }
    __syncthreads();
    if (i < N_NODES) {
        int incl = sh[t] + s_prefix;
        g_off[i + 1] = incl;
        g_cursor[i]  = incl - v;
        if (i == 0) g_off[0] = 0;
        g_outnorm[i] = rsqrtf(fmaxf((float)g_outdeg[i], 1.0f));
        g_innorm [i] = rsqrtf(fmaxf((float)v, 1.0f));
    }
}

// 4 edges per thread -> MLP=4 on the ATOMG return path
__global__ void k_scatter(const int* __restrict__ esrc, const int* __restrict__ edst) {
    int e0 = (blockIdx.x * blockDim.x + threadIdx.x) * 4;
    int d[4], p[4], s[4];
    #pragma unroll
    for (int q = 0; q < 4; q++) {
        int e = e0 + q;
        if (e < N_EDGES) {
            d[q] = edst[e]; s[q] = esrc[e];
            p[q] = atomicAdd(&g_cursor[d[q]], 1);
        } else p[q] = -1;
    }
    #pragma unroll
    for (int q = 0; q < 4; q++)
        if (p[q] >= 0) g_csr[p[q]] = s[q];
}

// ---------------- WMMA tf32 GEMM (R4 mainloop structure, fp16 in/out) --------
// Y_half[M,BN] = ((A * outnorm[:,None]) @ W); A fp32 (L1) or fp16 g_hh (L2).
// BM=128, BK=32, 256 thr / 8 warps (4M x 2N), warp tile 32 x BN/2.
template <int BN, int KT, int LAYER>
__global__ void __launch_bounds__(256) k_wmma_gemm(const float* __restrict__ Ain,
                                                   const float* __restrict__ W) {
    constexpr int BM  = 128;
    constexpr int BK  = 32;
    constexpr int LDA = 40;
    constexpr int LDB = BN + 4;
    constexpr int WN  = BN / 2;
    constexpr int FN  = WN / 16;

    extern __shared__ float smem[];
    float* sA = smem;                 // BM*LDA
    float* sB = sA + BM * LDA;        // BK*LDB
    float* stage = smem;              // epilogue staging aliases buffers

    const int tid  = threadIdx.x;
    const int wid  = tid >> 5;
    const int lane = tid & 31;
    const int wm   = wid >> 1;
    const int wn   = wid & 1;
    const int m0   = blockIdx.x * BM;

    wmma::fragment<wmma::accumulator, 16, 16, 8, float> c[2][FN];
    #pragma unroll
    for (int i = 0; i < 2; i++)
        #pragma unroll
        for (int j = 0; j < FN; j++) wmma::fill_fragment(c[i][j], 0.0f);

    const int arow  = tid >> 1;
    const int acol0 = (tid & 1) * 16;
    const int growA = m0 + arow;
    const bool okA  = growA < N_NODES;
    const float sc  = okA ? g_outnorm[growA] : 0.0f;

    for (int k0 = 0; k0 < KT; k0 += BK) {
        __syncthreads();
        // --- stage A (scaled + tf32-rounded) ---
        if constexpr (LAYER == 1) {
            const float* Arow = Ain + (size_t)growA * KT + k0 + acol0;
            #pragma unroll
            for (int q = 0; q < 4; q++) {
                float4 v = okA ? *(const float4*)(Arow + q * 4)
                               : make_float4(0.f, 0.f, 0.f, 0.f);
                float4 t;
                t.x = tf32_rna_f(v.x * sc);
                t.y = tf32_rna_f(v.y * sc);
                t.z = tf32_rna_f(v.z * sc);
                t.w = tf32_rna_f(v.w * sc);
                *(float4*)&sA[arow * LDA + acol0 + q * 4] = t;
            }
        } else {
            const __half* Arow = g_hh + (size_t)growA * KT + k0 + acol0;
            #pragma unroll
            for (int q = 0; q < 2; q++) {
                uint4 u = okA ? *(const uint4*)(Arow + q * 8)
                              : make_uint4(0u, 0u, 0u, 0u);
                const uint32_t uu[4] = { u.x, u.y, u.z, u.w };
                #pragma unroll
                for (int p = 0; p < 4; p++) {
                    float2 f = __half22float2(*(const __half2*)&uu[p]);
                    float2 t;
                    t.x = tf32_rna_f(f.x * sc);
                    t.y = tf32_rna_f(f.y * sc);
                    *(float2*)&sA[arow * LDA + acol0 + q * 8 + p * 2] = t;
                }
            }
        }
        // --- stage B (tf32-rounded); W is [KT x BN] row-major ---
        #pragma unroll
        for (int i = tid; i < BK * (BN / 4); i += 256) {
            int r = i / (BN / 4);
            int cc = (i % (BN / 4)) * 4;
            float4 v = *(const float4*)&W[(size_t)(k0 + r) * BN + cc];
            float4 t;
            t.x = tf32_rna_f(v.x);
            t.y = tf32_rna_f(v.y);
            t.z = tf32_rna_f(v.z);
            t.w = tf32_rna_f(v.w);
            *(float4*)&sB[r * LDB + cc] = t;
        }
        __syncthreads();

        // --- compute ---
        #pragma unroll
        for (int kk = 0; kk < BK; kk += 8) {
            wmma::fragment<wmma::matrix_a, 16, 16, 8, wmma::precision::tf32, wmma::row_major> a[2];
            wmma::fragment<wmma::matrix_b, 16, 16, 8, wmma::precision::tf32, wmma::row_major> bf[FN];
            #pragma unroll
            for (int i = 0; i < 2; i++)
                wmma::load_matrix_sync(a[i], &sA[(wm * 32 + i * 16) * LDA + kk], LDA);
            #pragma unroll
            for (int j = 0; j < FN; j++)
                wmma::load_matrix_sync(bf[j], &sB[kk * LDB + wn * WN + j * 16], LDB);
            #pragma unroll
            for (int i = 0; i < 2; i++)
                #pragma unroll
                for (int j = 0; j < FN; j++)
                    wmma::mma_sync(c[i][j], a[i], bf[j], c[i][j]);
        }
    }

    // --- epilogue: frags -> per-warp smem tile -> half2 global ---
    __syncthreads();   // mainloop smem reads done before aliasing as stage
    __half* Yh = (LAYER == 1) ? g_y1h : g_y2h;
    float* wtile = stage + wid * (32 * WN);
    #pragma unroll
    for (int i = 0; i < 2; i++)
        #pragma unroll
        for (int j = 0; j < FN; j++)
            wmma::store_matrix_sync(wtile + i * 16 * WN + j * 16, c[i][j], WN,
                                    wmma::mem_row_major);
    __syncwarp();
    {
        const float* srow = wtile + lane * WN;
        __half* drow = Yh + (size_t)(m0 + wm * 32 + lane) * BN + wn * WN;
        #pragma unroll
        for (int k2 = 0; k2 < WN / 2; k2++) {
            float2 f = *(const float2*)(srow + k2 * 2);
            *(__half2*)(drow + k2 * 2) = __float22half2_rn(f);
        }
    }
}

// ---------------- aggregation (CSR gather, fp16 payload) ---------------------
__global__ void __launch_bounds__(256) k_agg1(const float* __restrict__ b1) {
    int warp = (blockIdx.x * blockDim.x + threadIdx.x) >> 5;
    int lane = threadIdx.x & 31;
    if (warp >= N_NODES) return;
    int beg = g_off[warp], end = g_off[warp + 1];
    float4 acc = make_float4(0.f, 0.f, 0.f, 0.f);
    int j = beg;
    for (; j + 2 <= end; j += 2) {
        int s0 = g_csr[j], s1 = g_csr[j + 1];
        uint2 u0 = *(const uint2*)&g_y1h[(size_t)s0 * F_HID + lane * 4];
        uint2 u1 = *(const uint2*)&g_y1h[(size_t)s1 * F_HID + lane * 4];
        float2 a0 = __half22float2(*(const __half2*)&u0.x);
        float2 a1 = __half22float2(*(const __half2*)&u0.y);
        float2 b0 = __half22float2(*(const __half2*)&u1.x);
        float2 b1v = __half22float2(*(const __half2*)&u1.y);
        acc.x += a0.x + b0.x; acc.y += a0.y + b0.y;
        acc.z += a1.x + b1v.x; acc.w += a1.y + b1v.y;
    }
    if (j < end) {
        int s = g_csr[j];
        uint2 u = *(const uint2*)&g_y1h[(size_t)s * F_HID + lane * 4];
        float2 f0 = __half22float2(*(const __half2*)&u.x);
        float2 f1 = __half22float2(*(const __half2*)&u.y);
        acc.x += f0.x; acc.y += f0.y; acc.z += f1.x; acc.w += f1.y;
    }
    float inn = g_innorm[warp];
    float4 bb = *(const float4*)&b1[lane * 4];
    float2 o0, o1;
    o0.x = fmaxf(fmaf(acc.x, inn, bb.x), 0.f);
    o0.y = fmaxf(fmaf(acc.y, inn, bb.y), 0.f);
    o1.x = fmaxf(fmaf(acc.z, inn, bb.z), 0.f);
    o1.y = fmaxf(fmaf(acc.w, inn, bb.w), 0.f);
    uint2 u;
    *(__half2*)&u.x = __float22half2_rn(o0);
    *(__half2*)&u.y = __float22half2_rn(o1);
    *(uint2*)&g_hh[(size_t)warp * F_HID + lane * 4] = u;
}

__global__ void __launch_bounds__(256) k_agg2(const float* __restrict__ b2,
                                              float* __restrict__ out) {
    int warp = (blockIdx.x * blockDim.x + threadIdx.x) >> 5;
    int lane = threadIdx.x & 31;
    if (warp >= N_NODES) return;
    int beg = g_off[warp], end = g_off[warp + 1];
    float2 acc = make_float2(0.f, 0.f);
    int j = beg;
    for (; j + 2 <= end; j += 2) {
        int s0 = g_csr[j], s1 = g_csr[j + 1];
        float2 f0 = __half22float2(*(const __half2*)&g_y2h[(size_t)s0 * F_OUT + lane * 2]);
        float2 f1 = __half22float2(*(const __half2*)&g_y2h[(size_t)s1 * F_OUT + lane * 2]);
        acc.x += f0.x + f1.x; acc.y += f0.y + f1.y;
    }
    if (j < end) {
        float2 f = __half22float2(*(const __half2*)&g_y2h[(size_t)g_csr[j] * F_OUT + lane * 2]);
        acc.x += f.x; acc.y += f.y;
    }
    float inn = g_innorm[warp];
    float2 bb = *(const float2*)&b2[lane * 2];
    float2 o;
    o.x = fmaf(acc.x, inn, bb.x);
    o.y = fmaf(acc.y, inn, bb.y);
    *(float2*)&out[(size_t)warp * F_OUT + lane * 2] = o;
}

// ---------------- launch -----------------------------------------------------
extern "C" void kernel_launch(void* const* d_in, const int* in_sizes, int n_in,
                              void* d_out, int out_size) {
    const float* features = (const float*)d_in[0];
    const int*   esrc     = (const int*)  d_in[1];
    const int*   edst     = (const int*)  d_in[2];
    const float* W1       = (const float*)d_in[3];
    const float* b1       = (const float*)d_in[4];
    const float* W2       = (const float*)d_in[5];
    const float* b2       = (const float*)d_in[6];
    float* out = (float*)d_out;

    const int EB  = (N_EDGES + 255) / 256;       // 3125
    const int EB4 = (N_EDGES + 1023) / 1024;     // 782 (4 edges/thread)
    const int GB  = (N_NODES + 127) / 128;       // 391

    // dynamic smem: max(mainloop, epilogue) floats
    const int SM1 = 16384 * 4;  // 65536 B (epilogue 8*32*64 dominates)
    const int SM2 = 8192 * 4;   // 32768 B (epilogue 8*32*32 dominates)
    cudaFuncSetAttribute(k_wmma_gemm<128, 512, 1>,
                         cudaFuncAttributeMaxDynamicSharedMemorySize, SM1);
    cudaFuncSetAttribute(k_wmma_gemm<64, 128, 2>,
                         cudaFuncAttributeMaxDynamicSharedMemorySize, SM2);

    k_zero_deg  <<<NBLK, 256>>>();
    k_degrees   <<<EB, 256>>>(esrc, edst);
    k_scan_fused<<<NBLK, 256>>>();
    k_scatter   <<<EB4, 256>>>(esrc, edst);

    k_wmma_gemm<128, 512, 1><<<GB, 256, SM1>>>(features, W1);
    k_agg1<<<(N_NODES * 32 + 255) / 256, 256>>>(b1);
    k_wmma_gemm<64, 128, 2><<<GB, 256, SM2>>>(nullptr, W2);
    k_agg2<<<(N_NODES * 32 + 255) / 256, 256>>>(b2, out);
}